// round 1
// baseline (speedup 1.0000x reference)
#include <cuda_runtime.h>

#define NN 50000
#define NE 800000
#define FIN 16
#define FE 8
#define HD 8
#define NG 512

// Scratch (allocation-free: __device__ globals).
// g_Y4:   per-node factor table Y[n][o][a], 50000*64 f32 = 12.8MB (L2-resident)
// g_base4: per-node base term (root path + bias + edge-MLP bias path)
// g_agg4: scatter-add accumulators for layer 1 / layer 2
__device__ float4 g_Y4[NN * 16];
__device__ float4 g_base4[NN * 2];
__device__ float4 g_agg4[2][NN * 2];

__global__ void k_init(float* __restrict__ out, const float* __restrict__ blast) {
    int i = blockIdx.x * blockDim.x + threadIdx.x;
    float4 z = make_float4(0.f, 0.f, 0.f, 0.f);
    if (i < NN * 2) { g_agg4[0][i] = z; g_agg4[1][i] = z; }
    if (i < NG) out[i] = blast[0];
}

// Layer-1 per-node precompute:
//   Y1[n][o][a] = sum_i x[n,i] * We1[a, i*8+o]
//   base1[n][o] = b1[o] + sum_i x[n,i] * (root1[i,o] + be1[i*8+o])
__global__ void k_node1(const float* __restrict__ x, const float* __restrict__ We1,
                        const float* __restrict__ be1, const float* __restrict__ root1,
                        const float* __restrict__ b1) {
    __shared__ float4 sW[FIN * 16];   // transposed: [i][o][a]
    __shared__ float sWc[FIN * HD];   // root1 + be1 : [i][o]
    __shared__ float sb[HD];
    for (int t = threadIdx.x; t < FIN * 64; t += blockDim.x) {
        int i = t >> 6, o = (t >> 3) & 7, a = t & 7;
        ((float*)sW)[t] = We1[a * (FIN * HD) + i * HD + o];
    }
    for (int t = threadIdx.x; t < FIN * HD; t += blockDim.x)
        sWc[t] = root1[t] + be1[t];
    if (threadIdx.x < HD) sb[threadIdx.x] = b1[threadIdx.x];
    __syncthreads();

    int n = blockIdx.x * blockDim.x + threadIdx.x;
    if (n >= NN) return;

    float xv[FIN];
    const float4* xp = (const float4*)(x + n * FIN);
    #pragma unroll
    for (int q = 0; q < 4; q++) {
        float4 v = xp[q];
        xv[q * 4 + 0] = v.x; xv[q * 4 + 1] = v.y;
        xv[q * 4 + 2] = v.z; xv[q * 4 + 3] = v.w;
    }

    float4 acc[16];
    #pragma unroll
    for (int v = 0; v < 16; v++) acc[v] = make_float4(0.f, 0.f, 0.f, 0.f);
    for (int i = 0; i < FIN; i++) {
        float xi = xv[i];
        #pragma unroll
        for (int v = 0; v < 16; v++) {
            float4 w = sW[i * 16 + v];
            acc[v].x = fmaf(xi, w.x, acc[v].x);
            acc[v].y = fmaf(xi, w.y, acc[v].y);
            acc[v].z = fmaf(xi, w.z, acc[v].z);
            acc[v].w = fmaf(xi, w.w, acc[v].w);
        }
    }

    float bacc[HD];
    #pragma unroll
    for (int o = 0; o < HD; o++) bacc[o] = sb[o];
    for (int i = 0; i < FIN; i++) {
        float xi = xv[i];
        #pragma unroll
        for (int o = 0; o < HD; o++) bacc[o] = fmaf(xi, sWc[i * HD + o], bacc[o]);
    }

    float4* yp = g_Y4 + n * 16;
    #pragma unroll
    for (int v = 0; v < 16; v++) yp[v] = acc[v];
    g_base4[n * 2 + 0] = make_float4(bacc[0], bacc[1], bacc[2], bacc[3]);
    g_base4[n * 2 + 1] = make_float4(bacc[4], bacc[5], bacc[6], bacc[7]);
}

// Edge scatter: 8 threads per edge (lane o). msg[e,o] = sum_a ea[e,a]*Y[src][o][a];
// atomic scatter-add into agg[layer][dst*8+o]. Y row is 256B contiguous across
// the edge's 8 lanes -> minimal L1tex wavefronts; Y table is L2-resident.
__global__ void k_edge(const int* __restrict__ ei, const float* __restrict__ ea, int layer) {
    int gid = blockIdx.x * blockDim.x + threadIdx.x;
    int e = gid >> 3, o = gid & 7;
    int src = ei[e];
    int dst = ei[NE + e];
    const float4* eap = (const float4*)(ea + e * FE);
    float4 e0 = eap[0], e1 = eap[1];
    const float4* yp = g_Y4 + src * 16 + o * 2;
    float4 y0 = yp[0], y1 = yp[1];
    float m = e0.x * y0.x + e0.y * y0.y + e0.z * y0.z + e0.w * y0.w
            + e1.x * y1.x + e1.y * y1.y + e1.z * y1.z + e1.w * y1.w;
    float* agg = (float*)(layer ? g_agg4[1] : g_agg4[0]);
    atomicAdd(agg + dst * HD + o, m);
}

// h1 = relu(agg1 + base1); then layer-2 per-node precompute:
//   Y2[n][o][a] = sum_i h1[i] * We2[a, i*8+o]
//   base2[n][o] = b2[o] + sum_i h1[i] * (root2[i,o] + be2[i*8+o])
// (overwrites g_Y4 / g_base4 in place — same thread, same indices)
__global__ void k_node2(const float* __restrict__ We2, const float* __restrict__ be2,
                        const float* __restrict__ root2, const float* __restrict__ b2) {
    __shared__ float4 sW[HD * 16];    // [i][o][a]
    __shared__ float sWc[HD * HD];
    __shared__ float sb[HD];
    for (int t = threadIdx.x; t < HD * 64; t += blockDim.x) {
        int i = t >> 6, o = (t >> 3) & 7, a = t & 7;
        ((float*)sW)[t] = We2[a * (HD * HD) + i * HD + o];
    }
    for (int t = threadIdx.x; t < HD * HD; t += blockDim.x)
        sWc[t] = root2[t] + be2[t];
    if (threadIdx.x < HD) sb[threadIdx.x] = b2[threadIdx.x];
    __syncthreads();

    int n = blockIdx.x * blockDim.x + threadIdx.x;
    if (n >= NN) return;

    float h[HD];
    {
        float4 a0 = g_agg4[0][n * 2 + 0], a1 = g_agg4[0][n * 2 + 1];
        float4 c0 = g_base4[n * 2 + 0],  c1 = g_base4[n * 2 + 1];
        h[0] = fmaxf(a0.x + c0.x, 0.f); h[1] = fmaxf(a0.y + c0.y, 0.f);
        h[2] = fmaxf(a0.z + c0.z, 0.f); h[3] = fmaxf(a0.w + c0.w, 0.f);
        h[4] = fmaxf(a1.x + c1.x, 0.f); h[5] = fmaxf(a1.y + c1.y, 0.f);
        h[6] = fmaxf(a1.z + c1.z, 0.f); h[7] = fmaxf(a1.w + c1.w, 0.f);
    }

    float4 acc[16];
    #pragma unroll
    for (int v = 0; v < 16; v++) acc[v] = make_float4(0.f, 0.f, 0.f, 0.f);
    for (int i = 0; i < HD; i++) {
        float hi = h[i];
        #pragma unroll
        for (int v = 0; v < 16; v++) {
            float4 w = sW[i * 16 + v];
            acc[v].x = fmaf(hi, w.x, acc[v].x);
            acc[v].y = fmaf(hi, w.y, acc[v].y);
            acc[v].z = fmaf(hi, w.z, acc[v].z);
            acc[v].w = fmaf(hi, w.w, acc[v].w);
        }
    }

    float bacc[HD];
    #pragma unroll
    for (int o = 0; o < HD; o++) bacc[o] = sb[o];
    for (int i = 0; i < HD; i++) {
        float hi = h[i];
        #pragma unroll
        for (int o = 0; o < HD; o++) bacc[o] = fmaf(hi, sWc[i * HD + o], bacc[o]);
    }

    float4* yp = g_Y4 + n * 16;
    #pragma unroll
    for (int v = 0; v < 16; v++) yp[v] = acc[v];
    g_base4[n * 2 + 0] = make_float4(bacc[0], bacc[1], bacc[2], bacc[3]);
    g_base4[n * 2 + 1] = make_float4(bacc[4], bacc[5], bacc[6], bacc[7]);
}

// h2 = relu(agg2 + base2); out[batch[n]] += sum_o h2[o]*Wlast[o]
// (out pre-initialized to blast in k_init)
__global__ void k_pool(const int* __restrict__ batch, const float* __restrict__ Wlast,
                       float* __restrict__ out) {
    int n = blockIdx.x * blockDim.x + threadIdx.x;
    if (n >= NN) return;
    float4 a0 = g_agg4[1][n * 2 + 0], a1 = g_agg4[1][n * 2 + 1];
    float4 c0 = g_base4[n * 2 + 0],  c1 = g_base4[n * 2 + 1];
    float s = fmaxf(a0.x + c0.x, 0.f) * __ldg(Wlast + 0)
            + fmaxf(a0.y + c0.y, 0.f) * __ldg(Wlast + 1)
            + fmaxf(a0.z + c0.z, 0.f) * __ldg(Wlast + 2)
            + fmaxf(a0.w + c0.w, 0.f) * __ldg(Wlast + 3)
            + fmaxf(a1.x + c1.x, 0.f) * __ldg(Wlast + 4)
            + fmaxf(a1.y + c1.y, 0.f) * __ldg(Wlast + 5)
            + fmaxf(a1.z + c1.z, 0.f) * __ldg(Wlast + 6)
            + fmaxf(a1.w + c1.w, 0.f) * __ldg(Wlast + 7);
    atomicAdd(out + batch[n], s);
}

extern "C" void kernel_launch(void* const* d_in, const int* in_sizes, int n_in,
                              void* d_out, int out_size) {
    const float* x     = (const float*)d_in[0];
    const int*   ei    = (const int*)  d_in[1];
    const float* ea    = (const float*)d_in[2];
    const int*   batch = (const int*)  d_in[3];
    const float* We1   = (const float*)d_in[4];
    const float* be1   = (const float*)d_in[5];
    const float* root1 = (const float*)d_in[6];
    const float* b1    = (const float*)d_in[7];
    const float* We2   = (const float*)d_in[8];
    const float* be2   = (const float*)d_in[9];
    const float* root2 = (const float*)d_in[10];
    const float* b2    = (const float*)d_in[11];
    const float* Wlast = (const float*)d_in[12];
    const float* blast = (const float*)d_in[13];
    float* out = (float*)d_out;

    k_init <<<(NN * 2 + 255) / 256, 256>>>(out, blast);
    k_node1<<<(NN + 255) / 256, 256>>>(x, We1, be1, root1, b1);
    k_edge <<<(NE * 8) / 256, 256>>>(ei, ea, 0);
    k_node2<<<(NN + 255) / 256, 256>>>(We2, be2, root2, b2);
    k_edge <<<(NE * 8) / 256, 256>>>(ei, ea, 1);
    k_pool <<<(NN + 255) / 256, 256>>>(batch, Wlast, out);
}